// round 13
// baseline (speedup 1.0000x reference)
#include <cuda_runtime.h>
#include <cuda_fp16.h>
#include <mma.h>
#include <math.h>

using namespace nvcuda;

// Problem constants
#define T_TOK   4096      // BATCH*SEQ
#define SEQLEN  2048
#define HID     2048
#define NQH     16
#define NKVH    8
#define HD      128
#define QKVW    6144      // 4096 (q+gate) + 1024 (k) + 1024 (v)
#define KDIM    2048

// ---------------------------------------------------------------------------
// Scratch (device globals — no allocation allowed)
// ---------------------------------------------------------------------------
__device__ float  g_qkv[(size_t)T_TOK * QKVW];          // fp32 qkv+gate (GEMM out)
__device__ __half g_xh[(size_t)T_TOK * HID];            // x fp16
__device__ __half g_bt[(size_t)QKVW * KDIM];            // [Wq|Wk|Wv]^T fp16 [6144][2048]
__device__ __half g_bo[(size_t)HID * KDIM];             // Wo^T fp16 [2048][2048]
__device__ __half g_qh[(size_t)T_TOK * NQH * HD];       // q (norm+rope) fp16
__device__ __half g_kh[(size_t)T_TOK * NKVH * HD];      // k (norm+rope) fp16
__device__ __half g_vh[(size_t)T_TOK * NKVH * HD];      // v fp16
__device__ __half g_ah[(size_t)T_TOK * HID];            // attn out fp16

__device__ __forceinline__ void cpa16(void* smem_dst, const void* gmem_src) {
    unsigned s = (unsigned)__cvta_generic_to_shared(smem_dst);
    asm volatile("cp.async.cg.shared.global [%0], [%1], 16;" :: "r"(s), "l"(gmem_src));
}
#define CPA_COMMIT asm volatile("cp.async.commit_group;")
#define CPA_WAIT(n) asm volatile("cp.async.wait_group %0;" :: "n"(n))

// ---------------------------------------------------------------------------
// Prep: x fp32 -> fp16
// ---------------------------------------------------------------------------
__global__ __launch_bounds__(256) void conv_x(
    const float* __restrict__ in, __half* __restrict__ o, int n)
{
    for (int i = blockIdx.x * blockDim.x + threadIdx.x; i < n; i += gridDim.x * blockDim.x)
        o[i] = __float2half(in[i]);
}

// Prep: transpose + fp16: W [K=2048][N] fp32 -> out [N][K=2048] half
__global__ __launch_bounds__(256) void tconv(
    const float* __restrict__ W, __half* __restrict__ o, int N)
{
    __shared__ float t[32][33];
    const int n0 = blockIdx.x * 32, k0 = blockIdx.y * 32;
    const int tx = threadIdx.x, ty = threadIdx.y;
#pragma unroll
    for (int j = 0; j < 4; j++)
        t[ty + j * 8][tx] = W[(size_t)(k0 + ty + j * 8) * N + n0 + tx];
    __syncthreads();
#pragma unroll
    for (int j = 0; j < 4; j++)
        o[(size_t)(n0 + ty + j * 8) * KDIM + k0 + tx] = __float2half(t[tx][ty + j * 8]);
}

// ---------------------------------------------------------------------------
// fp16 single-pass GEMM: C[M,N] = A[M,K] * B^T   (B stored [N][K] fp16)
// CTA 128x256, 256 threads (8 warps 2x4, each 64x64), K-step 32, 3-stage.
// grid: (N/256, M/128). K = 2048 fixed.
// ---------------------------------------------------------------------------
#define GST (10240 + 20480)       // A 128x40x2 | B 256x40x2
#define G_A 0
#define G_B 10240
#define G_TOTAL (3 * GST)         // 92160
#define NKSTEP 64                 // 2048 / 32

__global__ __launch_bounds__(256) void gemm_h1(
    const __half* __restrict__ A, const __half* __restrict__ B,
    float* __restrict__ C, int ldc)
{
    extern __shared__ __align__(16) char gsm[];
    const int tid = threadIdx.x;
    const int w   = tid >> 5;
    const int wm  = w & 1;       // 2 row halves of 64
    const int wn  = w >> 1;      // 4 col quarters of 64
    const int m0 = blockIdx.y * 128;
    const int n0 = blockIdx.x * 256;

    wmma::fragment<wmma::accumulator, 16, 16, 16, float> acc[4][4];
#pragma unroll
    for (int i = 0; i < 4; i++)
#pragma unroll
        for (int j = 0; j < 4; j++)
            wmma::fill_fragment(acc[i][j], 0.0f);

    // stage loader: A 128 rows x 4 granules; B 256 rows x 4 granules
    auto load_stage = [&](int st, int k0) {
        char* s = gsm + st * GST;
#pragma unroll
        for (int t = 0; t < 2; t++) {
            int g = tid + t * 256;          // 0..511
            int r = g >> 2, q = g & 3;
            cpa16(s + G_A + (r * 40 + q * 8) * 2, A + (size_t)(m0 + r) * KDIM + k0 + q * 8);
        }
#pragma unroll
        for (int t = 0; t < 4; t++) {
            int g = tid + t * 256;          // 0..1023
            int r = g >> 2, q = g & 3;
            cpa16(s + G_B + (r * 40 + q * 8) * 2, B + (size_t)(n0 + r) * KDIM + k0 + q * 8);
        }
        CPA_COMMIT;
    };

    load_stage(0, 0);
    load_stage(1, 32);

    for (int kt = 0; kt < NKSTEP; kt++) {
        if (kt == NKSTEP - 1) { CPA_WAIT(0); } else { CPA_WAIT(1); }
        __syncthreads();
        if (kt + 2 < NKSTEP) load_stage((kt + 2) % 3, (kt + 2) * 32);

        const __half* sA = (const __half*)(gsm + (kt % 3) * GST + G_A);
        const __half* sB = (const __half*)(gsm + (kt % 3) * GST + G_B);

#pragma unroll
        for (int kk = 0; kk < 32; kk += 16) {
            wmma::fragment<wmma::matrix_a, 16, 16, 16, __half, wmma::row_major> af[4];
            wmma::fragment<wmma::matrix_b, 16, 16, 16, __half, wmma::col_major> bf[4];
#pragma unroll
            for (int i = 0; i < 4; i++)
                wmma::load_matrix_sync(af[i], sA + (wm * 64 + i * 16) * 40 + kk, 40);
#pragma unroll
            for (int j = 0; j < 4; j++)
                wmma::load_matrix_sync(bf[j], sB + (wn * 64 + j * 16) * 40 + kk, 40);
#pragma unroll
            for (int i = 0; i < 4; i++)
#pragma unroll
                for (int j = 0; j < 4; j++)
                    wmma::mma_sync(acc[i][j], af[i], bf[j], acc[i][j]);
        }
    }

#pragma unroll
    for (int i = 0; i < 4; i++)
#pragma unroll
        for (int j = 0; j < 4; j++)
            wmma::store_matrix_sync(
                C + (size_t)(m0 + wm * 64 + i * 16) * ldc + n0 + wn * 64 + j * 16,
                acc[i][j], ldc, wmma::mem_row_major);
}

// ---------------------------------------------------------------------------
// RMSNorm + partial RoPE; emits q/k/v fp16 (unchanged)
// ---------------------------------------------------------------------------
__global__ __launch_bounds__(128) void normrope_kernel(
    const float* __restrict__ qkv,
    __half* __restrict__ qh, __half* __restrict__ kh, __half* __restrict__ vh,
    const float* __restrict__ qnw, const float* __restrict__ knw,
    const int* __restrict__ positions)
{
    const int t  = blockIdx.x;
    const int hh = blockIdx.y;
    const int d  = threadIdx.x;

    if (hh >= NQH + NKVH) {
        int kvh = hh - NQH - NKVH;
        float v = qkv[(size_t)t * QKVW + 5120 + kvh * HD + d];
        vh[((size_t)t * NKVH + kvh) * HD + d] = __float2half(v);
        return;
    }

    const float* vec;
    const float* w;
    __half* outp;
    if (hh < NQH) {
        vec = qkv + (size_t)t * QKVW + hh * 256;
        w = qnw;
        outp = qh + ((size_t)t * NQH + hh) * HD;
    } else {
        int kvh = hh - NQH;
        vec = qkv + (size_t)t * QKVW + 4096 + kvh * HD;
        w = knw;
        outp = kh + ((size_t)t * NKVH + kvh) * HD;
    }

    float x = vec[d];

    __shared__ float sred[4];
    __shared__ float sv[128];
    int lane = d & 31, wrp = d >> 5;
    float ss = x * x;
#pragma unroll
    for (int o = 16; o > 0; o >>= 1) ss += __shfl_xor_sync(0xffffffffu, ss, o);
    if (lane == 0) sred[wrp] = ss;
    __syncthreads();
    float tot = sred[0] + sred[1] + sred[2] + sred[3];
    float r = rsqrtf(tot * (1.0f / 128.0f) + 1e-6f);
    float y = x * r * (1.0f + w[d]);

    sv[d] = y;
    __syncthreads();

    float out = y;
    if (d < 32) {
        int j = d & 15;
        float inv = powf(10000000.0f, -(float)j * (1.0f / 16.0f));
        float ang = (float)positions[t] * inv;
        float c = cosf(ang), s = sinf(ang);
        int base = (d < 16) ? d : (d - 16);
        float x1 = sv[base];
        float x2 = sv[base + 16];
        out = (d < 16) ? (x1 * c - x2 * s) : (x1 * s + x2 * c);
    }
    outp[d] = __float2half(out);
}

// ---------------------------------------------------------------------------
// fp16 tensor-core flash attention, cp.async double-buffered K/V.
// BQ=BK=64, 256 threads, 8 warps. Q/K/V/P fp16; S/O fp32.  (round-10 version)
// ---------------------------------------------------------------------------
#define AQ_LD 136
#define AS_LD 68
#define AP_LD 72
#define AO_LD 132
#define OFF_Q   0
#define OFF_K0  17408
#define OFF_K1  34816
#define OFF_V0  52224
#define OFF_V1  69632
#define OFF_P   87040
#define OFF_S   96256
#define OFF_O   113664
#define OFF_RED 147456
#define OFF_RM  148480
#define OFF_RL  148736
#define OFF_RA  148992
#define ATT_SMEM 149248

__global__ __launch_bounds__(256) void attn_h(
    const __half* __restrict__ qh, const __half* __restrict__ kh,
    const __half* __restrict__ vh, const float* __restrict__ qkv,
    const int* __restrict__ amask,
    __half* __restrict__ ao)
{
    extern __shared__ __align__(16) char asm_[];
    __half* Qs  = (__half*)(asm_ + OFF_Q);
    __half* Ks0 = (__half*)(asm_ + OFF_K0);
    __half* Ks1 = (__half*)(asm_ + OFF_K1);
    __half* Vs0 = (__half*)(asm_ + OFF_V0);
    __half* Vs1 = (__half*)(asm_ + OFF_V1);
    __half* Ps  = (__half*)(asm_ + OFF_P);
    float*  Ss  = (float*)(asm_ + OFF_S);
    float*  Os  = (float*)(asm_ + OFF_O);
    float*  red = (float*)(asm_ + OFF_RED);
    float*  rowm = (float*)(asm_ + OFF_RM);
    float*  rowl = (float*)(asm_ + OFF_RL);
    float*  rowa = (float*)(asm_ + OFF_RA);

    const int qt = (int)gridDim.x - 1 - (int)blockIdx.x;
    const int h  = blockIdx.y;
    const int b  = blockIdx.z;
    const int kvh = h >> 1;

    const __half* Qb = qh + ((size_t)b * SEQLEN * NQH + h) * HD;
    const __half* Kb = kh + ((size_t)b * SEQLEN * NKVH + kvh) * HD;
    const __half* Vb = vh + ((size_t)b * SEQLEN * NKVH + kvh) * HD;
    const float*  Gb = qkv + (size_t)b * SEQLEN * QKVW + h * 256 + 128;
    const int*    mk = amask + b * SEQLEN;

    const int tid = threadIdx.x;
    const int w   = tid >> 5;
    const int wr  = w & 3;
    const int wc  = w >> 2;

#pragma unroll
    for (int t = 0; t < 4; t++) {
        int g = tid + t * 256;
        int r = g >> 4, q = g & 15;
        cpa16(Ks0 + r * AQ_LD + q * 8, Kb + (size_t)r * (NKVH * HD) + q * 8);
        cpa16(Vs0 + r * AQ_LD + q * 8, Vb + (size_t)r * (NKVH * HD) + q * 8);
    }
    CPA_COMMIT;

#pragma unroll
    for (int t = 0; t < 4; t++) {
        int g = tid + t * 256;
        int r = g >> 4, q = g & 15;
        cpa16(Qs + r * AQ_LD + q * 8, Qb + (size_t)(qt * 64 + r) * (NQH * HD) + q * 8);
    }
    CPA_COMMIT;
    for (int i = tid; i < 64 * 32; i += 256) {
        int r = i >> 5, c4 = (i & 31) * 4;
        *(float4*)(Os + r * AO_LD + c4) = make_float4(0.f, 0.f, 0.f, 0.f);
    }
    if (tid < 64) { rowm[tid] = -1e30f; rowl[tid] = 0.0f; }

    const float scale = 0.08838834764831845f;

    for (int kt = 0; kt <= qt; kt++) {
        const int buf = kt & 1;
        if (kt < qt) {
            __half* Kn = (buf ^ 1) ? Ks1 : Ks0;
            __half* Vn = (buf ^ 1) ? Vs1 : Vs0;
            const size_t row0 = (size_t)(kt + 1) * 64;
#pragma unroll
            for (int t = 0; t < 4; t++) {
                int g = tid + t * 256;
                int r = g >> 4, q = g & 15;
                cpa16(Kn + r * AQ_LD + q * 8, Kb + (row0 + r) * (NKVH * HD) + q * 8);
                cpa16(Vn + r * AQ_LD + q * 8, Vb + (row0 + r) * (NKVH * HD) + q * 8);
            }
            CPA_COMMIT;
            CPA_WAIT(1);
        } else {
            CPA_WAIT(0);
        }
        __syncthreads();

        const __half* Kt = buf ? Ks1 : Ks0;
        const __half* Vt = buf ? Vs1 : Vs0;

        // S = Q K^T
        {
            wmma::fragment<wmma::accumulator, 16, 16, 16, float> sacc[2];
            wmma::fill_fragment(sacc[0], 0.0f);
            wmma::fill_fragment(sacc[1], 0.0f);
#pragma unroll
            for (int kk = 0; kk < 128; kk += 16) {
                wmma::fragment<wmma::matrix_a, 16, 16, 16, __half, wmma::row_major> af;
                wmma::load_matrix_sync(af, Qs + wr * 16 * AQ_LD + kk, AQ_LD);
#pragma unroll
                for (int j = 0; j < 2; j++) {
                    wmma::fragment<wmma::matrix_b, 16, 16, 16, __half, wmma::col_major> bf;
                    wmma::load_matrix_sync(bf, Kt + (wc * 32 + j * 16) * AQ_LD + kk, AQ_LD);
                    wmma::mma_sync(sacc[j], af, bf, sacc[j]);
                }
            }
            wmma::store_matrix_sync(Ss + wr * 16 * AS_LD + wc * 32,      sacc[0], AS_LD, wmma::mem_row_major);
            wmma::store_matrix_sync(Ss + wr * 16 * AS_LD + wc * 32 + 16, sacc[1], AS_LD, wmma::mem_row_major);
        }
        __syncthreads();

        // Pass 1: scale + mask + partial row max
        {
            int r = tid & 63, part = tid >> 6;
            int sq = qt * 64 + r;
            float pm = -1e30f;
#pragma unroll
            for (int j = 0; j < 16; j++) {
                int col = part * 16 + j;
                int sk = kt * 64 + col;
                float val = Ss[r * AS_LD + col] * scale;
                if (sk > sq || mk[sk] == 0) val = -1e30f;
                Ss[r * AS_LD + col] = val;
                pm = fmaxf(pm, val);
            }
            red[part * 64 + r] = pm;
        }
        __syncthreads();
        if (tid < 64) {
            float mnew = fmaxf(fmaxf(red[tid], red[64 + tid]),
                               fmaxf(red[128 + tid], red[192 + tid]));
            mnew = fmaxf(mnew, rowm[tid]);
            rowa[tid] = __expf(rowm[tid] - mnew);
            rowm[tid] = mnew;
        }
        __syncthreads();

        // Pass 2: exponentiate -> P (fp16), partial sums
        {
            int r = tid & 63, part = tid >> 6;
            float m = rowm[r];
            float psum = 0.0f;
#pragma unroll
            for (int j = 0; j < 16; j++) {
                int col = part * 16 + j;
                __half ph = __float2half(__expf(Ss[r * AS_LD + col] - m));
                Ps[r * AP_LD + col] = ph;
                psum += __half2float(ph);
            }
            red[part * 64 + r] = psum;
        }
        __syncthreads();
        if (tid < 64)
            rowl[tid] = rowl[tid] * rowa[tid]
                      + red[tid] + red[64 + tid] + red[128 + tid] + red[192 + tid];
        // Rescale O by alpha
        for (int i = tid; i < 64 * 32; i += 256) {
            int r = i >> 5, c4 = (i & 31) * 4;
            float a = rowa[r];
            float4 o4 = *(float4*)(Os + r * AO_LD + c4);
            o4.x *= a; o4.y *= a; o4.z *= a; o4.w *= a;
            *(float4*)(Os + r * AO_LD + c4) = o4;
        }
        __syncthreads();

        // O += P V
        {
            wmma::fragment<wmma::accumulator, 16, 16, 16, float> oacc[4];
#pragma unroll
            for (int j = 0; j < 4; j++)
                wmma::load_matrix_sync(oacc[j], Os + wr * 16 * AO_LD + wc * 64 + j * 16,
                                       AO_LD, wmma::mem_row_major);
#pragma unroll
            for (int kk = 0; kk < 64; kk += 16) {
                wmma::fragment<wmma::matrix_a, 16, 16, 16, __half, wmma::row_major> af;
                wmma::load_matrix_sync(af, Ps + wr * 16 * AP_LD + kk, AP_LD);
#pragma unroll
                for (int j = 0; j < 4; j++) {
                    wmma::fragment<wmma::matrix_b, 16, 16, 16, __half, wmma::row_major> bf;
                    wmma::load_matrix_sync(bf, Vt + kk * AQ_LD + wc * 64 + j * 16, AQ_LD);
                    wmma::mma_sync(oacc[j], af, bf, oacc[j]);
                }
            }
#pragma unroll
            for (int j = 0; j < 4; j++)
                wmma::store_matrix_sync(Os + wr * 16 * AO_LD + wc * 64 + j * 16, oacc[j],
                                        AO_LD, wmma::mem_row_major);
        }
        __syncthreads();
    }

    // Epilogue: normalize, sigmoid-gate, write fp16
    for (int i = tid; i < 64 * 32; i += 256) {
        int r = i >> 5, c4 = (i & 31) * 4;
        int s = qt * 64 + r;
        float inv = 1.0f / rowl[r];
        float4 g4 = *(const float4*)(Gb + (size_t)s * QKVW + c4);
        float4 o4 = *(float4*)(Os + r * AO_LD + c4);
        size_t idx = ((size_t)b * SEQLEN + s) * HID + h * HD + c4;
        ao[idx]     = __float2half(o4.x * inv * (1.0f / (1.0f + __expf(-g4.x))));
        ao[idx + 1] = __float2half(o4.y * inv * (1.0f / (1.0f + __expf(-g4.y))));
        ao[idx + 2] = __float2half(o4.z * inv * (1.0f / (1.0f + __expf(-g4.z))));
        ao[idx + 3] = __float2half(o4.w * inv * (1.0f / (1.0f + __expf(-g4.w))));
    }
}

// ---------------------------------------------------------------------------
extern "C" void kernel_launch(void* const* d_in, const int* in_sizes, int n_in,
                              void* d_out, int out_size)
{
    const float* x     = (const float*)d_in[0];
    const int*   amask = (const int*)  d_in[1];
    const int*   pos   = (const int*)  d_in[2];
    const float* Wq    = (const float*)d_in[3];
    const float* Wk    = (const float*)d_in[4];
    const float* Wv    = (const float*)d_in[5];
    const float* Wo    = (const float*)d_in[6];
    const float* qnw   = (const float*)d_in[7];
    const float* knw   = (const float*)d_in[8];
    float* out = (float*)d_out;

    void *p_qkv, *p_xh, *p_bt, *p_bo, *p_qh, *p_kh, *p_vh, *p_ah;
    cudaGetSymbolAddress(&p_qkv, g_qkv);
    cudaGetSymbolAddress(&p_xh,  g_xh);
    cudaGetSymbolAddress(&p_bt,  g_bt);
    cudaGetSymbolAddress(&p_bo,  g_bo);
    cudaGetSymbolAddress(&p_qh,  g_qh);
    cudaGetSymbolAddress(&p_kh,  g_kh);
    cudaGetSymbolAddress(&p_vh,  g_vh);
    cudaGetSymbolAddress(&p_ah,  g_ah);
    float*  qkv = (float*)p_qkv;
    __half* xh  = (__half*)p_xh;
    __half* bt  = (__half*)p_bt;
    __half* bo  = (__half*)p_bo;
    __half* qh  = (__half*)p_qh;
    __half* kh  = (__half*)p_kh;
    __half* vh  = (__half*)p_vh;
    __half* ah  = (__half*)p_ah;

    // 0) Prep: convert x; transpose+convert weights
    conv_x<<<1184, 256>>>(x, xh, T_TOK * HID);
    tconv<<<dim3(4096 / 32, KDIM / 32), dim3(32, 8)>>>(Wq, bt, 4096);
    tconv<<<dim3(1024 / 32, KDIM / 32), dim3(32, 8)>>>(Wk, bt + (size_t)4096 * KDIM, 1024);
    tconv<<<dim3(1024 / 32, KDIM / 32), dim3(32, 8)>>>(Wv, bt + (size_t)5120 * KDIM, 1024);
    tconv<<<dim3(2048 / 32, KDIM / 32), dim3(32, 8)>>>(Wo, bo, 2048);

    // 1) QKV+gate projection -> g_qkv fp32 [4096][6144]
    cudaFuncSetAttribute(gemm_h1, cudaFuncAttributeMaxDynamicSharedMemorySize, G_TOTAL);
    gemm_h1<<<dim3(24, 32), 256, G_TOTAL>>>(xh, bt, qkv, QKVW);

    // 2) RMSNorm + RoPE -> fp16 q/k/v
    normrope_kernel<<<dim3(T_TOK, 32), 128>>>(qkv, qh, kh, vh, qnw, knw, pos);

    // 3) fp16 flash attention + sigmoid gate -> fp16
    cudaFuncSetAttribute(attn_h, cudaFuncAttributeMaxDynamicSharedMemorySize, ATT_SMEM);
    attn_h<<<dim3(SEQLEN / 64, NQH, 2), 256, ATT_SMEM>>>(qh, kh, vh, qkv, amask, ah);

    // 4) Output projection -> d_out fp32
    gemm_h1<<<dim3(8, 32), 256, G_TOTAL>>>(ah, bo, out, HID);
}

// round 15
// speedup vs baseline: 1.7454x; 1.7454x over previous
#include <cuda_runtime.h>
#include <cuda_fp16.h>
#include <mma.h>
#include <math.h>

using namespace nvcuda;

// Problem constants
#define T_TOK   4096      // BATCH*SEQ
#define SEQLEN  2048
#define HID     2048
#define NQH     16
#define NKVH    8
#define HD      128
#define QKVW    6144      // 4096 (q+gate) + 1024 (k) + 1024 (v)
#define KDIM    2048

// ---------------------------------------------------------------------------
// Scratch (device globals — no allocation allowed)
// ---------------------------------------------------------------------------
__device__ float  g_qkv[(size_t)T_TOK * QKVW];          // fp32 qkv+gate (GEMM out)
__device__ __half g_xh[(size_t)T_TOK * HID];            // x fp16
__device__ __half g_bt[(size_t)QKVW * KDIM];            // [Wq|Wk|Wv]^T fp16 [6144][2048]
__device__ __half g_bo[(size_t)HID * KDIM];             // Wo^T fp16 [2048][2048]
__device__ __half g_qh[(size_t)T_TOK * NQH * HD];       // q (norm+rope) fp16
__device__ __half g_kh[(size_t)T_TOK * NKVH * HD];      // k (norm+rope) fp16
__device__ __half g_vh[(size_t)T_TOK * NKVH * HD];      // v fp16
__device__ __half g_ah[(size_t)T_TOK * HID];            // attn out fp16

__device__ __forceinline__ void cpa16(void* smem_dst, const void* gmem_src) {
    unsigned s = (unsigned)__cvta_generic_to_shared(smem_dst);
    asm volatile("cp.async.cg.shared.global [%0], [%1], 16;" :: "r"(s), "l"(gmem_src));
}
#define CPA_COMMIT asm volatile("cp.async.commit_group;")
#define CPA_WAIT(n) asm volatile("cp.async.wait_group %0;" :: "n"(n))

// ---------------------------------------------------------------------------
// Prep: x fp32 -> fp16
// ---------------------------------------------------------------------------
__global__ __launch_bounds__(256) void conv_x(
    const float* __restrict__ in, __half* __restrict__ o, int n)
{
    for (int i = blockIdx.x * blockDim.x + threadIdx.x; i < n; i += gridDim.x * blockDim.x)
        o[i] = __float2half(in[i]);
}

// Prep: transpose + fp16: W [K=2048][N] fp32 -> out [N][K=2048] half
__global__ __launch_bounds__(256) void tconv(
    const float* __restrict__ W, __half* __restrict__ o, int N)
{
    __shared__ float t[32][33];
    const int n0 = blockIdx.x * 32, k0 = blockIdx.y * 32;
    const int tx = threadIdx.x, ty = threadIdx.y;
#pragma unroll
    for (int j = 0; j < 4; j++)
        t[ty + j * 8][tx] = W[(size_t)(k0 + ty + j * 8) * N + n0 + tx];
    __syncthreads();
#pragma unroll
    for (int j = 0; j < 4; j++)
        o[(size_t)(n0 + ty + j * 8) * KDIM + k0 + tx] = __float2half(t[tx][ty + j * 8]);
}

// ---------------------------------------------------------------------------
// fp16 single-pass GEMM (EXACT round-10 config: CTA 128x128, 128 thr, 3-stage)
// ---------------------------------------------------------------------------
#define GST 20480
#define G_A 0
#define G_B 10240
#define G_TOTAL (3 * GST)
#define NKSTEP 64

__global__ __launch_bounds__(128) void gemm_h1(
    const __half* __restrict__ A, const __half* __restrict__ B,
    float* __restrict__ C, int ldc)
{
    extern __shared__ __align__(16) char gsm[];
    const int tid = threadIdx.x;
    const int w   = tid >> 5;
    const int wm  = w & 1;
    const int wn  = w >> 1;
    const int m0 = blockIdx.y * 128;
    const int n0 = blockIdx.x * 128;

    wmma::fragment<wmma::accumulator, 16, 16, 16, float> acc[4][4];
#pragma unroll
    for (int i = 0; i < 4; i++)
#pragma unroll
        for (int j = 0; j < 4; j++)
            wmma::fill_fragment(acc[i][j], 0.0f);

    auto load_stage = [&](int st, int k0) {
        char* s = gsm + st * GST;
#pragma unroll
        for (int t = 0; t < 4; t++) {
            int g = tid + t * 128;
            int r = g >> 2, q = g & 3;
            cpa16(s + G_A + (r * 40 + q * 8) * 2, A + (size_t)(m0 + r) * KDIM + k0 + q * 8);
            cpa16(s + G_B + (r * 40 + q * 8) * 2, B + (size_t)(n0 + r) * KDIM + k0 + q * 8);
        }
        CPA_COMMIT;
    };

    load_stage(0, 0);
    load_stage(1, 32);

    for (int kt = 0; kt < NKSTEP; kt++) {
        if (kt == NKSTEP - 1) { CPA_WAIT(0); } else { CPA_WAIT(1); }
        __syncthreads();
        if (kt + 2 < NKSTEP) load_stage((kt + 2) % 3, (kt + 2) * 32);

        const __half* sA = (const __half*)(gsm + (kt % 3) * GST + G_A);
        const __half* sB = (const __half*)(gsm + (kt % 3) * GST + G_B);

#pragma unroll
        for (int kk = 0; kk < 32; kk += 16) {
            wmma::fragment<wmma::matrix_a, 16, 16, 16, __half, wmma::row_major> af[4];
            wmma::fragment<wmma::matrix_b, 16, 16, 16, __half, wmma::col_major> bf[4];
#pragma unroll
            for (int i = 0; i < 4; i++)
                wmma::load_matrix_sync(af[i], sA + (wm * 64 + i * 16) * 40 + kk, 40);
#pragma unroll
            for (int j = 0; j < 4; j++)
                wmma::load_matrix_sync(bf[j], sB + (wn * 64 + j * 16) * 40 + kk, 40);
#pragma unroll
            for (int i = 0; i < 4; i++)
#pragma unroll
                for (int j = 0; j < 4; j++)
                    wmma::mma_sync(acc[i][j], af[i], bf[j], acc[i][j]);
        }
    }

#pragma unroll
    for (int i = 0; i < 4; i++)
#pragma unroll
        for (int j = 0; j < 4; j++)
            wmma::store_matrix_sync(
                C + (size_t)(m0 + wm * 64 + i * 16) * ldc + n0 + wn * 64 + j * 16,
                acc[i][j], ldc, wmma::mem_row_major);
}

// ---------------------------------------------------------------------------
// RMSNorm + partial RoPE; emits q/k/v fp16 (unchanged)
// ---------------------------------------------------------------------------
__global__ __launch_bounds__(128) void normrope_kernel(
    const float* __restrict__ qkv,
    __half* __restrict__ qh, __half* __restrict__ kh, __half* __restrict__ vh,
    const float* __restrict__ qnw, const float* __restrict__ knw,
    const int* __restrict__ positions)
{
    const int t  = blockIdx.x;
    const int hh = blockIdx.y;
    const int d  = threadIdx.x;

    if (hh >= NQH + NKVH) {
        int kvh = hh - NQH - NKVH;
        float v = qkv[(size_t)t * QKVW + 5120 + kvh * HD + d];
        vh[((size_t)t * NKVH + kvh) * HD + d] = __float2half(v);
        return;
    }

    const float* vec;
    const float* w;
    __half* outp;
    if (hh < NQH) {
        vec = qkv + (size_t)t * QKVW + hh * 256;
        w = qnw;
        outp = qh + ((size_t)t * NQH + hh) * HD;
    } else {
        int kvh = hh - NQH;
        vec = qkv + (size_t)t * QKVW + 4096 + kvh * HD;
        w = knw;
        outp = kh + ((size_t)t * NKVH + kvh) * HD;
    }

    float x = vec[d];

    __shared__ float sred[4];
    __shared__ float sv[128];
    int lane = d & 31, wrp = d >> 5;
    float ss = x * x;
#pragma unroll
    for (int o = 16; o > 0; o >>= 1) ss += __shfl_xor_sync(0xffffffffu, ss, o);
    if (lane == 0) sred[wrp] = ss;
    __syncthreads();
    float tot = sred[0] + sred[1] + sred[2] + sred[3];
    float r = rsqrtf(tot * (1.0f / 128.0f) + 1e-6f);
    float y = x * r * (1.0f + w[d]);

    sv[d] = y;
    __syncthreads();

    float out = y;
    if (d < 32) {
        int j = d & 15;
        float inv = powf(10000000.0f, -(float)j * (1.0f / 16.0f));
        float ang = (float)positions[t] * inv;
        float c = cosf(ang), s = sinf(ang);
        int base = (d < 16) ? d : (d - 16);
        float x1 = sv[base];
        float x2 = sv[base + 16];
        out = (d < 16) ? (x1 * c - x2 * s) : (x1 * s + x2 * c);
    }
    outp[d] = __float2half(out);
}

// ---------------------------------------------------------------------------
// fp16 tensor-core flash attention — single-buffered K/V (smem 114432 B ->
// 2 CTAs/SM), mid-iteration K/V re-prefetch, per-warp O rescale.
// BQ=BK=64, 256 threads, 8 warps.
// ---------------------------------------------------------------------------
#define AQ_LD 136
#define AS_LD 68
#define AP_LD 72
#define AO_LD 132
#define OFF_Q   0
#define OFF_K   17408
#define OFF_V   34816
#define OFF_P   52224
#define OFF_S   61440
#define OFF_O   78848
#define OFF_RED 112640
#define OFF_RM  113664
#define OFF_RL  113920
#define OFF_RA  114176
#define ATT_SMEM 114432

__global__ __launch_bounds__(256) void attn_h(
    const __half* __restrict__ qh, const __half* __restrict__ kh,
    const __half* __restrict__ vh, const float* __restrict__ qkv,
    const int* __restrict__ amask,
    __half* __restrict__ ao)
{
    extern __shared__ __align__(16) char asm_[];
    __half* Qs  = (__half*)(asm_ + OFF_Q);
    __half* Ks  = (__half*)(asm_ + OFF_K);
    __half* Vs  = (__half*)(asm_ + OFF_V);
    __half* Ps  = (__half*)(asm_ + OFF_P);
    float*  Ss  = (float*)(asm_ + OFF_S);
    float*  Os  = (float*)(asm_ + OFF_O);
    float*  red = (float*)(asm_ + OFF_RED);
    float*  rowm = (float*)(asm_ + OFF_RM);
    float*  rowl = (float*)(asm_ + OFF_RL);
    float*  rowa = (float*)(asm_ + OFF_RA);

    const int qt = (int)gridDim.x - 1 - (int)blockIdx.x;
    const int h  = blockIdx.y;
    const int b  = blockIdx.z;
    const int kvh = h >> 1;

    const __half* Qb = qh + ((size_t)b * SEQLEN * NQH + h) * HD;
    const __half* Kb = kh + ((size_t)b * SEQLEN * NKVH + kvh) * HD;
    const __half* Vb = vh + ((size_t)b * SEQLEN * NKVH + kvh) * HD;
    const float*  Gb = qkv + (size_t)b * SEQLEN * QKVW + h * 256 + 128;
    const int*    mk = amask + b * SEQLEN;

    const int tid = threadIdx.x;
    const int w   = tid >> 5;
    const int lane = tid & 31;
    const int wr  = w & 3;
    const int wc  = w >> 2;

    // Preload K0, V0, Q
#pragma unroll
    for (int t = 0; t < 4; t++) {
        int g = tid + t * 256;
        int r = g >> 4, q = g & 15;
        cpa16(Ks + r * AQ_LD + q * 8, Kb + (size_t)r * (NKVH * HD) + q * 8);
        cpa16(Vs + r * AQ_LD + q * 8, Vb + (size_t)r * (NKVH * HD) + q * 8);
        cpa16(Qs + r * AQ_LD + q * 8, Qb + (size_t)(qt * 64 + r) * (NQH * HD) + q * 8);
    }
    CPA_COMMIT;
    for (int i = tid; i < 64 * 32; i += 256) {
        int r = i >> 5, c4 = (i & 31) * 4;
        *(float4*)(Os + r * AO_LD + c4) = make_float4(0.f, 0.f, 0.f, 0.f);
    }
    if (tid < 64) { rowm[tid] = -1e30f; rowl[tid] = 0.0f; }

    const float scale = 0.08838834764831845f;

    for (int kt = 0; kt <= qt; kt++) {
        CPA_WAIT(0);
        __syncthreads();                       // sync1: K,V (and Q on iter 0) visible

        // S = Q K^T
        {
            wmma::fragment<wmma::accumulator, 16, 16, 16, float> sacc[2];
            wmma::fill_fragment(sacc[0], 0.0f);
            wmma::fill_fragment(sacc[1], 0.0f);
#pragma unroll
            for (int kk = 0; kk < 128; kk += 16) {
                wmma::fragment<wmma::matrix_a, 16, 16, 16, __half, wmma::row_major> af;
                wmma::load_matrix_sync(af, Qs + wr * 16 * AQ_LD + kk, AQ_LD);
#pragma unroll
                for (int j = 0; j < 2; j++) {
                    wmma::fragment<wmma::matrix_b, 16, 16, 16, __half, wmma::col_major> bf;
                    wmma::load_matrix_sync(bf, Ks + (wc * 32 + j * 16) * AQ_LD + kk, AQ_LD);
                    wmma::mma_sync(sacc[j], af, bf, sacc[j]);
                }
            }
            wmma::store_matrix_sync(Ss + wr * 16 * AS_LD + wc * 32,      sacc[0], AS_LD, wmma::mem_row_major);
            wmma::store_matrix_sync(Ss + wr * 16 * AS_LD + wc * 32 + 16, sacc[1], AS_LD, wmma::mem_row_major);
        }
        __syncthreads();                       // sync2: S ready; K fully consumed

        // K buffer free — prefetch K for kt+1 (latency hidden behind softmax+PV)
        if (kt < qt) {
            const size_t row0 = (size_t)(kt + 1) * 64;
#pragma unroll
            for (int t = 0; t < 4; t++) {
                int g = tid + t * 256;
                int r = g >> 4, q = g & 15;
                cpa16(Ks + r * AQ_LD + q * 8, Kb + (row0 + r) * (NKVH * HD) + q * 8);
            }
            CPA_COMMIT;
        }

        // Pass 1: scale + mask + partial row max
        {
            int r = tid & 63, part = tid >> 6;
            int sq = qt * 64 + r;
            float pm = -1e30f;
#pragma unroll
            for (int j = 0; j < 16; j++) {
                int col = part * 16 + j;
                int sk = kt * 64 + col;
                float val = Ss[r * AS_LD + col] * scale;
                if (sk > sq || mk[sk] == 0) val = -1e30f;
                Ss[r * AS_LD + col] = val;
                pm = fmaxf(pm, val);
            }
            red[part * 64 + r] = pm;
        }
        __syncthreads();                       // sync3
        if (tid < 64) {
            float mnew = fmaxf(fmaxf(red[tid], red[64 + tid]),
                               fmaxf(red[128 + tid], red[192 + tid]));
            mnew = fmaxf(mnew, rowm[tid]);
            rowa[tid] = __expf(rowm[tid] - mnew);
            rowm[tid] = mnew;
        }
        __syncthreads();                       // sync4

        // Pass 2: exponentiate -> P (fp16), partial sums
        {
            int r = tid & 63, part = tid >> 6;
            float m = rowm[r];
            float psum = 0.0f;
#pragma unroll
            for (int j = 0; j < 16; j++) {
                int col = part * 16 + j;
                __half ph = __float2half(__expf(Ss[r * AS_LD + col] - m));
                Ps[r * AP_LD + col] = ph;
                psum += __half2float(ph);
            }
            red[part * 64 + r] = psum;
        }
        __syncthreads();                       // sync5

        if (tid < 64)
            rowl[tid] = rowl[tid] * rowa[tid]
                      + red[tid] + red[64 + tid] + red[128 + tid] + red[192 + tid];

        // Per-warp O rescale (own 16x64 region; rowa stable since sync4)
#pragma unroll
        for (int i = lane; i < 256; i += 32) {
            int r = wr * 16 + (i >> 4);
            int c4 = wc * 64 + (i & 15) * 4;
            float a = rowa[r];
            float4 o4 = *(float4*)(Os + r * AO_LD + c4);
            o4.x *= a; o4.y *= a; o4.z *= a; o4.w *= a;
            *(float4*)(Os + r * AO_LD + c4) = o4;
        }

        // O += P V  (own region; Ps ready since sync5)
        {
            wmma::fragment<wmma::accumulator, 16, 16, 16, float> oacc[4];
#pragma unroll
            for (int j = 0; j < 4; j++)
                wmma::load_matrix_sync(oacc[j], Os + wr * 16 * AO_LD + wc * 64 + j * 16,
                                       AO_LD, wmma::mem_row_major);
#pragma unroll
            for (int kk = 0; kk < 64; kk += 16) {
                wmma::fragment<wmma::matrix_a, 16, 16, 16, __half, wmma::row_major> af;
                wmma::load_matrix_sync(af, Ps + wr * 16 * AP_LD + kk, AP_LD);
#pragma unroll
                for (int j = 0; j < 4; j++) {
                    wmma::fragment<wmma::matrix_b, 16, 16, 16, __half, wmma::row_major> bf;
                    wmma::load_matrix_sync(bf, Vs + kk * AQ_LD + wc * 64 + j * 16, AQ_LD);
                    wmma::mma_sync(oacc[j], af, bf, oacc[j]);
                }
            }
#pragma unroll
            for (int j = 0; j < 4; j++)
                wmma::store_matrix_sync(Os + wr * 16 * AO_LD + wc * 64 + j * 16, oacc[j],
                                        AO_LD, wmma::mem_row_major);
        }
        __syncthreads();                       // sync6: PV done; V buffer free

        // Prefetch V for kt+1
        if (kt < qt) {
            const size_t row0 = (size_t)(kt + 1) * 64;
#pragma unroll
            for (int t = 0; t < 4; t++) {
                int g = tid + t * 256;
                int r = g >> 4, q = g & 15;
                cpa16(Vs + r * AQ_LD + q * 8, Vb + (row0 + r) * (NKVH * HD) + q * 8);
            }
            CPA_COMMIT;
        }
    }

    // Epilogue: normalize, sigmoid-gate, write fp16
    for (int i = tid; i < 64 * 32; i += 256) {
        int r = i >> 5, c4 = (i & 31) * 4;
        int s = qt * 64 + r;
        float inv = 1.0f / rowl[r];
        float4 g4 = *(const float4*)(Gb + (size_t)s * QKVW + c4);
        float4 o4 = *(float4*)(Os + r * AO_LD + c4);
        size_t idx = ((size_t)b * SEQLEN + s) * HID + h * HD + c4;
        ao[idx]     = __float2half(o4.x * inv * (1.0f / (1.0f + __expf(-g4.x))));
        ao[idx + 1] = __float2half(o4.y * inv * (1.0f / (1.0f + __expf(-g4.y))));
        ao[idx + 2] = __float2half(o4.z * inv * (1.0f / (1.0f + __expf(-g4.z))));
        ao[idx + 3] = __float2half(o4.w * inv * (1.0f / (1.0f + __expf(-g4.w))));
    }
}

// ---------------------------------------------------------------------------
extern "C" void kernel_launch(void* const* d_in, const int* in_sizes, int n_in,
                              void* d_out, int out_size)
{
    const float* x     = (const float*)d_in[0];
    const int*   amask = (const int*)  d_in[1];
    const int*   pos   = (const int*)  d_in[2];
    const float* Wq    = (const float*)d_in[3];
    const float* Wk    = (const float*)d_in[4];
    const float* Wv    = (const float*)d_in[5];
    const float* Wo    = (const float*)d_in[6];
    const float* qnw   = (const float*)d_in[7];
    const float* knw   = (const float*)d_in[8];
    float* out = (float*)d_out;

    void *p_qkv, *p_xh, *p_bt, *p_bo, *p_qh, *p_kh, *p_vh, *p_ah;
    cudaGetSymbolAddress(&p_qkv, g_qkv);
    cudaGetSymbolAddress(&p_xh,  g_xh);
    cudaGetSymbolAddress(&p_bt,  g_bt);
    cudaGetSymbolAddress(&p_bo,  g_bo);
    cudaGetSymbolAddress(&p_qh,  g_qh);
    cudaGetSymbolAddress(&p_kh,  g_kh);
    cudaGetSymbolAddress(&p_vh,  g_vh);
    cudaGetSymbolAddress(&p_ah,  g_ah);
    float*  qkv = (float*)p_qkv;
    __half* xh  = (__half*)p_xh;
    __half* bt  = (__half*)p_bt;
    __half* bo  = (__half*)p_bo;
    __half* qh  = (__half*)p_qh;
    __half* kh  = (__half*)p_kh;
    __half* vh  = (__half*)p_vh;
    __half* ah  = (__half*)p_ah;

    // 0) Prep: convert x; transpose+convert weights
    conv_x<<<1184, 256>>>(x, xh, T_TOK * HID);
    tconv<<<dim3(4096 / 32, KDIM / 32), dim3(32, 8)>>>(Wq, bt, 4096);
    tconv<<<dim3(1024 / 32, KDIM / 32), dim3(32, 8)>>>(Wk, bt + (size_t)4096 * KDIM, 1024);
    tconv<<<dim3(1024 / 32, KDIM / 32), dim3(32, 8)>>>(Wv, bt + (size_t)5120 * KDIM, 1024);
    tconv<<<dim3(2048 / 32, KDIM / 32), dim3(32, 8)>>>(Wo, bo, 2048);

    // 1) QKV+gate projection -> g_qkv fp32 [4096][6144]
    cudaFuncSetAttribute(gemm_h1, cudaFuncAttributeMaxDynamicSharedMemorySize, G_TOTAL);
    gemm_h1<<<dim3(48, 32), 128, G_TOTAL>>>(xh, bt, qkv, QKVW);

    // 2) RMSNorm + RoPE -> fp16 q/k/v
    normrope_kernel<<<dim3(T_TOK, 32), 128>>>(qkv, qh, kh, vh, qnw, knw, pos);

    // 3) fp16 flash attention + sigmoid gate -> fp16
    cudaFuncSetAttribute(attn_h, cudaFuncAttributeMaxDynamicSharedMemorySize, ATT_SMEM);
    attn_h<<<dim3(SEQLEN / 64, NQH, 2), 256, ATT_SMEM>>>(qh, kh, vh, qkv, amask, ah);

    // 4) Output projection -> d_out fp32
    gemm_h1<<<dim3(16, 32), 128, G_TOTAL>>>(ah, bo, out, HID);
}